// round 7
// baseline (speedup 1.0000x reference)
#include <cuda_runtime.h>
#include <stdint.h>

// XFlatRGBExtractorOp — masked channel select + stack, 256-bit accesses.
// B=16, H=W=1536. Output (B,3,H,W) f32.
//   ch0 = r_mask ? xtrans[:,0] : chroma_pred[:,0]
//   ch1 = green_pred[:,0]
//   ch2 = b_mask ? xtrans[:,2] : chroma_pred[:,1]
// Traffic floor 1.208 GB; kernel pinned at the B300 mixed-stream DRAM ceiling.
// This round: LDG.E.256 / STG.E.256 (sm_100+ v8.f32) to halve request count.

#define Bsz 16
#define H 1536
#define W 1536
#define P (H * W)          // 2359296 floats per plane
#define P8 (P / 8)         // 294912 float8 per plane = 1152 * 256 exactly
#define W8 (W / 8)         // 192 float8 per row

// 6-bit row masks: bit c set => take xtrans at column (w % 6) == c.
// R_POS rows: 0:{4} 1:{0,2} 2:{4} 3:{1} 4:{3,5} 5:{1}
// B_POS rows: 0:{1} 1:{3,5} 2:{1} 3:{4} 4:{0,2} 5:{4}
__constant__ unsigned c_rmask[6] = {0x10u, 0x05u, 0x10u, 0x02u, 0x28u, 0x02u};
__constant__ unsigned c_bmask[6] = {0x02u, 0x28u, 0x02u, 0x10u, 0x05u, 0x10u};

struct __align__(32) F8 { float v[8]; };

__device__ __forceinline__ F8 ldg256(const float* p) {
    F8 r;
    asm volatile("ld.global.v8.f32 {%0,%1,%2,%3,%4,%5,%6,%7}, [%8];"
                 : "=f"(r.v[0]), "=f"(r.v[1]), "=f"(r.v[2]), "=f"(r.v[3]),
                   "=f"(r.v[4]), "=f"(r.v[5]), "=f"(r.v[6]), "=f"(r.v[7])
                 : "l"(p));
    return r;
}

__device__ __forceinline__ void stg256(float* p, const F8& r) {
    asm volatile("st.global.v8.f32 [%0], {%1,%2,%3,%4,%5,%6,%7,%8};"
                 :: "l"(p),
                    "f"(r.v[0]), "f"(r.v[1]), "f"(r.v[2]), "f"(r.v[3]),
                    "f"(r.v[4]), "f"(r.v[5]), "f"(r.v[6]), "f"(r.v[7])
                 : "memory");
}

__global__ __launch_bounds__(256) void xflat_rgb_kernel(
    const float* __restrict__ green,    // B * P
    const float* __restrict__ xtrans,   // B * 3 * P
    const float* __restrict__ chroma,   // B * 2 * P
    float* __restrict__ out)            // B * 3 * P
{
    const int i = blockIdx.x * 256 + threadIdx.x;   // float8 index within plane
    const int plane = blockIdx.y;                   // 0..47
    const int b = plane / 3;
    const int c = plane - 3 * b;

    float* const op = out + ((size_t)plane * P8 + i) * 8;

    if (c == 1) {
        // green copy (uniform branch across the whole plane's blocks)
        F8 g = ldg256(green + ((size_t)b * P8 + i) * 8);
        stg256(op, g);
        return;
    }

    // row / column phase within the 6x6 tile
    const int h  = i / W8;
    const int w8 = (i - h * W8) * 8;                // starting column of this float8
    const int r  = h % 6;
    const int w6 = w8 % 6;                          // 0, 2, or 4

    const unsigned rowm = (c == 0) ? c_rmask[r] : c_bmask[r];
    // bit k of sel = mask for column residue (w6 + k) mod 6, k = 0..7
    const unsigned m12 = rowm | (rowm << 6);
    const unsigned sel = (m12 >> w6) & 0xFFu;

    const int xch = (c == 0) ? 0 : 2;               // xtrans channel
    const int pch = (c == 0) ? 0 : 1;               // chroma channel

    const F8 a = ldg256(xtrans + (((size_t)b * 3 + xch) * P8 + i) * 8);
    const F8 p = ldg256(chroma + (((size_t)b * 2 + pch) * P8 + i) * 8);

    F8 o;
#pragma unroll
    for (int k = 0; k < 8; ++k)
        o.v[k] = (sel >> k & 1u) ? a.v[k] : p.v[k];
    stg256(op, o);
}

extern "C" void kernel_launch(void* const* d_in, const int* in_sizes, int n_in,
                              void* d_out, int out_size)
{
    const float* green  = (const float*)d_in[0];    // (B,1,H,W)
    const float* xtrans = (const float*)d_in[1];    // (B,3,H,W)
    const float* chroma = (const float*)d_in[2];    // (B,2,H,W)
    float* out = (float*)d_out;                     // (B,3,H,W)

    dim3 grid(P8 / 256, Bsz * 3, 1);                // 1152 x 48 blocks
    xflat_rgb_kernel<<<grid, 256>>>(green, xtrans, chroma, out);
}